// round 1
// baseline (speedup 1.0000x reference)
#include <cuda_runtime.h>
#include <cstdint>

// ---------------------------------------------------------------------------
// TrainableTree: out[n] = a(x_n) * ( sin(Wt x_n + bt) . w_eff + c )
// where the whole linear tree after sin() is collapsed into (w_eff, c) by a
// tiny composition kernel (backward vector chain, output dim = 1).
// ---------------------------------------------------------------------------

__device__ float g_weff[64];
__device__ float g_c;

// ---------------- packed f32x2 helpers (sm_100+) ----------------
__device__ __forceinline__ unsigned long long pk2(float lo, float hi) {
    unsigned long long r;
    asm("mov.b64 %0, {%1, %2};" : "=l"(r) : "f"(lo), "f"(hi));
    return r;
}
__device__ __forceinline__ void upk2(unsigned long long v, float& lo, float& hi) {
    asm("mov.b64 {%0, %1}, %2;" : "=f"(lo), "=f"(hi) : "l"(v));
}
__device__ __forceinline__ unsigned long long f2fma(unsigned long long a,
                                                    unsigned long long b,
                                                    unsigned long long c) {
    unsigned long long d;
    asm("fma.rn.f32x2 %0, %1, %2, %3;" : "=l"(d) : "l"(a), "l"(b), "l"(c));
    return d;
}
__device__ __forceinline__ unsigned long long f2mul(unsigned long long a,
                                                    unsigned long long b) {
    unsigned long long d;
    asm("mul.rn.f32x2 %0, %1, %2;" : "=l"(d) : "l"(a), "l"(b));
    return d;
}

// ---------------------------------------------------------------------------
// Composition kernel: collapse the linear tree into w_eff[64] and scalar c.
//
//   res = Wr . (L1[0]+L1[1]) + br
//   L-levels are linear => res = s . w_eff + c with
//   g1[i][o] = sum_p Wr[p]        * W1[i][p][o]       (i = 0..1)
//   g2[j][o] = sum_p g1[j>>1][p]  * W2[j][p][o]       (j = 0..3)
//   g3[m][o] = sum_p g2[m>>1][p]  * W3[m][p][o]       (m = 0..7)
//   w_eff[m] = sum_k sum_o g3[k>>1][o] * Wleaf[k][o][m]   (k = 0..15)
//   c = br + Wr.(b1[0]+b1[1]) + sum_j g1[j>>1].b2[j]
//          + sum_m g2[m>>1].b3[m] + sum_k g3[k>>1].bleaf[k]
// Total ~180k MACs: trivially cheap, one CTA.
// ---------------------------------------------------------------------------
__global__ void __launch_bounds__(1024)
compose_kernel(const float* __restrict__ Wleaf, const float* __restrict__ bleaf,
               const float* __restrict__ W3, const float* __restrict__ b3,
               const float* __restrict__ W2, const float* __restrict__ b2,
               const float* __restrict__ W1, const float* __restrict__ b1,
               const float* __restrict__ Wr, const float* __restrict__ br) {
    __shared__ float gr[64];
    __shared__ float g1[2][64];
    __shared__ float g2[4][64];
    __shared__ float g3[8][64];
    __shared__ float part[16][64];
    __shared__ float cpart[64];

    const int t = threadIdx.x;  // 1024 threads

    if (t < 64) gr[t] = Wr[t];
    __syncthreads();

    if (t < 128) {
        const int i = t >> 6, o = t & 63;
        const float* W = W1 + i * 4096;
        float s = 0.f;
        #pragma unroll 8
        for (int p = 0; p < 64; p++) s = fmaf(W[p * 64 + o], gr[p], s);
        g1[i][o] = s;
    }
    __syncthreads();

    if (t < 256) {
        const int j = t >> 6, o = t & 63;
        const float* W = W2 + j * 4096;
        const float* g = g1[j >> 1];
        float s = 0.f;
        #pragma unroll 8
        for (int p = 0; p < 64; p++) s = fmaf(W[p * 64 + o], g[p], s);
        g2[j][o] = s;
    }
    __syncthreads();

    if (t < 512) {
        const int m = t >> 6, o = t & 63;
        const float* W = W3 + m * 4096;
        const float* g = g2[m >> 1];
        float s = 0.f;
        #pragma unroll 8
        for (int p = 0; p < 64; p++) s = fmaf(W[p * 64 + o], g[p], s);
        g3[m][o] = s;
    }
    __syncthreads();

    {   // leaves: 16 nodes x 64 outputs = 1024 threads
        const int k = t >> 6, m = t & 63;
        const float* W = Wleaf + k * 4096;     // Wleaf[k][o][m], sum over o
        const float* g = g3[k >> 1];
        float s = 0.f;
        #pragma unroll 8
        for (int o = 0; o < 64; o++) s = fmaf(W[o * 64 + m], g[o], s);
        part[k][m] = s;
    }
    __syncthreads();

    if (t < 64) {
        float s = 0.f;
        #pragma unroll
        for (int k = 0; k < 16; k++) s += part[k][t];
        g_weff[t] = s;
    }

    // bias composition
    if (t < 64) {
        const int o = t;
        float s = gr[o] * (b1[o] + b1[64 + o]);
        #pragma unroll
        for (int j = 0; j < 4; j++) s = fmaf(g1[j >> 1][o], b2[j * 64 + o], s);
        #pragma unroll
        for (int m = 0; m < 8; m++) s = fmaf(g2[m >> 1][o], b3[m * 64 + o], s);
        #pragma unroll
        for (int k = 0; k < 16; k++) s = fmaf(g3[k >> 1][o], bleaf[k * 64 + o], s);
        cpart[o] = s;
    }
    __syncthreads();

    if (t == 0) {
        float s = br[0];
        for (int o = 0; o < 64; o++) s += cpart[o];
        g_c = s;
    }
}

// ---------------------------------------------------------------------------
// Main kernel: one sample per thread, fully fused, packed f32x2 over the
// (i, i+1) pairs of the 64-dim hidden vector.
//   h_pair = bt_pair + sum_d wt2[d][ip] * {x_d, x_d}
//   sin via odd Taylor to x^7 (|h| <~ 1 -> rel err < 3e-6)
//   acc_pair += sin(h)_pair * weff_pair
// ---------------------------------------------------------------------------
__global__ void __launch_bounds__(256)
tree_main_kernel(const float* __restrict__ x, const float* __restrict__ Wt,
                 const float* __restrict__ bt, float* __restrict__ out, int N) {
    __shared__ unsigned long long wt2[10][32];   // {Wt[2i][d], Wt[2i+1][d]}
    __shared__ unsigned long long weff2[32];
    __shared__ unsigned long long bt2[32];

    const int t = threadIdx.x;

    for (int idx = t; idx < 320; idx += 256) {
        const int d = idx / 32, ip = idx % 32;
        wt2[d][ip] = pk2(Wt[(2 * ip) * 10 + d], Wt[(2 * ip + 1) * 10 + d]);
    }
    if (t < 32) {
        weff2[t] = pk2(g_weff[2 * t], g_weff[2 * t + 1]);
        bt2[t]   = pk2(bt[2 * t], bt[2 * t + 1]);
    }
    __syncthreads();

    const int n = blockIdx.x * blockDim.x + t;
    if (n >= N) return;

    // ---- load x (10 floats, 8B-aligned) ----
    float xv[10];
    {
        const float2* x2 = reinterpret_cast<const float2*>(x + (size_t)n * 10);
        #pragma unroll
        for (int i = 0; i < 5; i++) {
            const float2 v = x2[i];
            xv[2 * i]     = v.x;
            xv[2 * i + 1] = v.y;
        }
    }

    // ---- envelope a = prod(x^2 - 1) / sqrt(1000 + a^2) ----
    float a = fmaf(xv[0], xv[0], -1.0f);
    #pragma unroll
    for (int d = 1; d < 10; d++) a *= fmaf(xv[d], xv[d], -1.0f);
    a = a * rsqrtf(fmaf(a, a, 1000.0f));

    // ---- broadcast-packed x and Taylor constants ----
    unsigned long long xd[10];
    #pragma unroll
    for (int d = 0; d < 10; d++) xd[d] = pk2(xv[d], xv[d]);

    const unsigned long long C7  = pk2(-1.9841270e-4f, -1.9841270e-4f);  // -1/5040
    const unsigned long long C5  = pk2( 8.3333333e-3f,  8.3333333e-3f);  //  1/120
    const unsigned long long C3  = pk2(-1.6666667e-1f, -1.6666667e-1f);  // -1/6
    const unsigned long long ONE = pk2(1.0f, 1.0f);

    // ---- fused h -> sin -> dot ----
    unsigned long long acc = pk2(0.0f, 0.0f);
    #pragma unroll
    for (int ip = 0; ip < 32; ip++) {
        unsigned long long h = bt2[ip];
        #pragma unroll
        for (int d = 0; d < 10; d++) h = f2fma(wt2[d][ip], xd[d], h);
        const unsigned long long t2 = f2mul(h, h);
        unsigned long long p = f2fma(t2, C7, C5);
        p = f2fma(t2, p, C3);
        p = f2fma(t2, p, ONE);
        const unsigned long long s = f2mul(h, p);   // sin(h) pair
        acc = f2fma(s, weff2[ip], acc);
    }

    float alo, ahi;
    upk2(acc, alo, ahi);
    const float res = alo + ahi + g_c;
    out[n] = a * res;
}

// ---------------------------------------------------------------------------
extern "C" void kernel_launch(void* const* d_in, const int* in_sizes, int n_in,
                              void* d_out, int out_size) {
    const float* x     = (const float*)d_in[0];
    const float* Wt    = (const float*)d_in[1];
    const float* bt    = (const float*)d_in[2];
    const float* Wleaf = (const float*)d_in[3];
    const float* bleaf = (const float*)d_in[4];
    const float* W3    = (const float*)d_in[5];
    const float* b3    = (const float*)d_in[6];
    const float* W2    = (const float*)d_in[7];
    const float* b2    = (const float*)d_in[8];
    const float* W1    = (const float*)d_in[9];
    const float* b1    = (const float*)d_in[10];
    const float* Wr    = (const float*)d_in[11];
    const float* br    = (const float*)d_in[12];
    float* out = (float*)d_out;

    const int N = in_sizes[0] / 10;

    compose_kernel<<<1, 1024>>>(Wleaf, bleaf, W3, b3, W2, b2, W1, b1, Wr, br);

    const int threads = 256;
    const int blocks = (N + threads - 1) / threads;
    tree_main_kernel<<<blocks, threads>>>(x, Wt, bt, out, N);
}

// round 2
// speedup vs baseline: 1.0372x; 1.0372x over previous
#include <cuda_runtime.h>
#include <cstdint>

// ---------------------------------------------------------------------------
// TrainableTree: out[n] = a(x_n) * ( sin(Wt x_n + bt) . w_eff + c )
// The entire linear tree after sin() collapses into (w_eff[64], c) since
// OUT=1 and all tree ops are linear. Compose kernel builds the backward
// vector chain; main kernel is a fused 10->64 GEMV + poly-sin + dot.
// ---------------------------------------------------------------------------

__device__ float g_part[16][64];   // per-leaf partials of w_eff
__device__ float c_part[16];       // per-leaf partials of c (chain bias in [0])

// ---------------- packed f32x2 helpers (sm_100+) ----------------
__device__ __forceinline__ unsigned long long pk2(float lo, float hi) {
    unsigned long long r;
    asm("mov.b64 %0, {%1, %2};" : "=l"(r) : "f"(lo), "f"(hi));
    return r;
}
__device__ __forceinline__ void upk2(unsigned long long v, float& lo, float& hi) {
    asm("mov.b64 {%0, %1}, %2;" : "=f"(lo), "=f"(hi) : "l"(v));
}
__device__ __forceinline__ unsigned long long f2fma(unsigned long long a,
                                                    unsigned long long b,
                                                    unsigned long long c) {
    unsigned long long d;
    asm("fma.rn.f32x2 %0, %1, %2, %3;" : "=l"(d) : "l"(a), "l"(b), "l"(c));
    return d;
}
__device__ __forceinline__ unsigned long long f2mul(unsigned long long a,
                                                    unsigned long long b) {
    unsigned long long d;
    asm("mul.rn.f32x2 %0, %1, %2;" : "=l"(d) : "l"(a), "l"(b));
    return d;
}

// ---------------------------------------------------------------------------
// Compose: 16 blocks. Every block redundantly computes the tiny backward
// chain g1,g2,g3 (57k MACs), then block k does leaf k (the 256KB Wleaf read
// is the expensive part -> parallel across 16 SMs). No inter-block sync.
// ---------------------------------------------------------------------------
__global__ void __launch_bounds__(256)
compose_kernel(const float* __restrict__ Wleaf, const float* __restrict__ bleaf,
               const float* __restrict__ W3, const float* __restrict__ b3,
               const float* __restrict__ W2, const float* __restrict__ b2,
               const float* __restrict__ W1, const float* __restrict__ b1,
               const float* __restrict__ Wr, const float* __restrict__ br) {
    __shared__ float gr[64];
    __shared__ float g1[2][64];
    __shared__ float g2[4][64];
    __shared__ float g3[8][64];
    __shared__ float cp[64];

    const int t = threadIdx.x;       // 256 threads
    const int k = blockIdx.x;        // leaf id 0..15

    if (t < 64) gr[t] = Wr[t];
    __syncthreads();

    if (t < 128) {
        const int i = t >> 6, o = t & 63;
        const float* W = W1 + i * 4096;
        float s = 0.f;
        #pragma unroll 8
        for (int p = 0; p < 64; p++) s = fmaf(W[p * 64 + o], gr[p], s);
        g1[i][o] = s;
    }
    __syncthreads();

    {
        const int j = t >> 6, o = t & 63;
        const float* W = W2 + j * 4096;
        const float* g = g1[j >> 1];
        float s = 0.f;
        #pragma unroll 8
        for (int p = 0; p < 64; p++) s = fmaf(W[p * 64 + o], g[p], s);
        g2[j][o] = s;
    }
    __syncthreads();

    #pragma unroll
    for (int r = 0; r < 2; r++) {
        const int idx = t + 256 * r;
        const int m = idx >> 6, o = idx & 63;
        const float* W = W3 + m * 4096;
        const float* g = g2[m >> 1];
        float s = 0.f;
        #pragma unroll 8
        for (int p = 0; p < 64; p++) s = fmaf(W[p * 64 + o], g[p], s);
        g3[m][o] = s;
    }
    __syncthreads();

    // leaf k: w_eff partial over m; sum over o of g3[k>>1][o]*Wleaf[k][o][m]
    // 256 threads: (m = t&63, quarter q = t>>2? ) -> use 4-way split over o
    {
        const int m = t & 63, q = t >> 6;           // q in 0..3
        const float* W = Wleaf + k * 4096;
        const float* g = g3[k >> 1];
        float s = 0.f;
        #pragma unroll
        for (int o = q * 16; o < q * 16 + 16; o++) s = fmaf(W[o * 64 + m], g[o], s);
        // reduce the 4 quarters via shared
        __shared__ float red[4][64];
        red[q][m] = s;
        __syncthreads();
        if (t < 64) g_part[k][t] = red[0][t] + red[1][t] + red[2][t] + red[3][t];
    }

    // c partials
    if (t < 64) {
        const int o = t;
        float s = g3[k >> 1][o] * bleaf[k * 64 + o];
        if (k == 0) {
            s += gr[o] * (b1[o] + b1[64 + o]);
            #pragma unroll
            for (int j = 0; j < 4; j++) s = fmaf(g1[j >> 1][o], b2[j * 64 + o], s);
            #pragma unroll
            for (int m = 0; m < 8; m++) s = fmaf(g2[m >> 1][o], b3[m * 64 + o], s);
        }
        cp[o] = s;
    }
    __syncthreads();
    if (t == 0) {
        float s = (k == 0) ? br[0] : 0.f;
        #pragma unroll 8
        for (int o = 0; o < 64; o++) s += cp[o];
        c_part[k] = s;
    }
}

// ---------------------------------------------------------------------------
// Main kernel: TWO samples per thread, packed f32x2 over hidden-dim pairs.
// Weight LDS amortized over both samples and vectorized (LDS.128 = 2 pairs).
// ---------------------------------------------------------------------------
__global__ void __launch_bounds__(256)
tree_main_kernel(const float* __restrict__ x, const float* __restrict__ Wt,
                 const float* __restrict__ bt, float* __restrict__ out, int N) {
    // wt4[ip][j] = { pair(d=2j), pair(d=2j+1) } where pair(d) = {Wt[2ip][d], Wt[2ip+1][d]}
    __shared__ ulonglong2 wt4[32][5];
    __shared__ unsigned long long weff2[32];
    __shared__ unsigned long long bt2[32];
    __shared__ float sw[64];
    __shared__ float s_c;

    const int t = threadIdx.x;

    if (t < 64) {
        float s = 0.f;
        #pragma unroll
        for (int k = 0; k < 16; k++) s += g_part[k][t];
        sw[t] = s;
    }
    if (t == 64) {
        float s = 0.f;
        #pragma unroll
        for (int k = 0; k < 16; k++) s += c_part[k];
        s_c = s;
    }
    for (int idx = t; idx < 320; idx += 256) {
        const int ip = idx / 10, d = idx % 10;
        reinterpret_cast<unsigned long long*>(wt4)[ip * 10 + d] =
            pk2(Wt[(2 * ip) * 10 + d], Wt[(2 * ip + 1) * 10 + d]);
    }
    __syncthreads();
    if (t < 32) {
        weff2[t] = pk2(sw[2 * t], sw[2 * t + 1]);
        bt2[t]   = pk2(bt[2 * t], bt[2 * t + 1]);
    }
    __syncthreads();

    const int s0 = blockIdx.x * 512 + t;     // sample A
    const int s1 = s0 + 256;                 // sample B
    if (s1 >= N) {
        if (s0 < N) { /* fallthrough handled below for tail (N divisible; keep simple) */ }
    }

    // ---- load x for both samples ----
    float xa[10], xb[10];
    {
        const float2* x2 = reinterpret_cast<const float2*>(x + (size_t)s0 * 10);
        #pragma unroll
        for (int i = 0; i < 5; i++) { float2 v = x2[i]; xa[2*i] = v.x; xa[2*i+1] = v.y; }
        const float2* y2 = reinterpret_cast<const float2*>(x + (size_t)s1 * 10);
        #pragma unroll
        for (int i = 0; i < 5; i++) { float2 v = y2[i]; xb[2*i] = v.x; xb[2*i+1] = v.y; }
    }

    // ---- envelopes ----
    float aA = fmaf(xa[0], xa[0], -1.0f);
    float aB = fmaf(xb[0], xb[0], -1.0f);
    #pragma unroll
    for (int d = 1; d < 10; d++) {
        aA *= fmaf(xa[d], xa[d], -1.0f);
        aB *= fmaf(xb[d], xb[d], -1.0f);
    }
    aA = aA * rsqrtf(fmaf(aA, aA, 1000.0f));
    aB = aB * rsqrtf(fmaf(aB, aB, 1000.0f));

    // ---- broadcast-packed x ----
    unsigned long long xdA[10], xdB[10];
    #pragma unroll
    for (int d = 0; d < 10; d++) { xdA[d] = pk2(xa[d], xa[d]); xdB[d] = pk2(xb[d], xb[d]); }

    const unsigned long long C7  = pk2(-1.9841270e-4f, -1.9841270e-4f);
    const unsigned long long C5  = pk2( 8.3333333e-3f,  8.3333333e-3f);
    const unsigned long long C3  = pk2(-1.6666667e-1f, -1.6666667e-1f);
    const unsigned long long ONE = pk2(1.0f, 1.0f);

    unsigned long long accA = pk2(0.f, 0.f), accB = pk2(0.f, 0.f);

    #pragma unroll 8
    for (int ip = 0; ip < 32; ip++) {
        unsigned long long hA = bt2[ip];
        unsigned long long hB = hA;
        #pragma unroll
        for (int j = 0; j < 5; j++) {
            const ulonglong2 w = wt4[ip][j];
            hA = f2fma(w.x, xdA[2 * j], hA);
            hB = f2fma(w.x, xdB[2 * j], hB);
            hA = f2fma(w.y, xdA[2 * j + 1], hA);
            hB = f2fma(w.y, xdB[2 * j + 1], hB);
        }
        const unsigned long long t2A = f2mul(hA, hA);
        const unsigned long long t2B = f2mul(hB, hB);
        unsigned long long pA = f2fma(t2A, C7, C5);
        unsigned long long pB = f2fma(t2B, C7, C5);
        pA = f2fma(t2A, pA, C3);
        pB = f2fma(t2B, pB, C3);
        pA = f2fma(t2A, pA, ONE);
        pB = f2fma(t2B, pB, ONE);
        const unsigned long long sA = f2mul(hA, pA);
        const unsigned long long sB = f2mul(hB, pB);
        const unsigned long long wv = weff2[ip];
        accA = f2fma(sA, wv, accA);
        accB = f2fma(sB, wv, accB);
    }

    float l0, h0, l1, h1;
    upk2(accA, l0, h0);
    upk2(accB, l1, h1);
    const float c = s_c;
    if (s0 < N) out[s0] = aA * (l0 + h0 + c);
    if (s1 < N) out[s1] = aB * (l1 + h1 + c);
}

// ---------------------------------------------------------------------------
extern "C" void kernel_launch(void* const* d_in, const int* in_sizes, int n_in,
                              void* d_out, int out_size) {
    const float* x     = (const float*)d_in[0];
    const float* Wt    = (const float*)d_in[1];
    const float* bt    = (const float*)d_in[2];
    const float* Wleaf = (const float*)d_in[3];
    const float* bleaf = (const float*)d_in[4];
    const float* W3    = (const float*)d_in[5];
    const float* b3    = (const float*)d_in[6];
    const float* W2    = (const float*)d_in[7];
    const float* b2    = (const float*)d_in[8];
    const float* W1    = (const float*)d_in[9];
    const float* b1    = (const float*)d_in[10];
    const float* Wr    = (const float*)d_in[11];
    const float* br    = (const float*)d_in[12];
    float* out = (float*)d_out;

    const int N = in_sizes[0] / 10;

    compose_kernel<<<16, 256>>>(Wleaf, bleaf, W3, b3, W2, b2, W1, b1, Wr, br);

    const int blocks = (N + 511) / 512;   // 2 samples per thread, 256 thr/blk
    tree_main_kernel<<<blocks, 256>>>(x, Wt, bt, out, N);
}

// round 4
// speedup vs baseline: 1.4545x; 1.4024x over previous
#include <cuda_runtime.h>
#include <cuda_bf16.h>
#include <cstdint>

// ===========================================================================
// TrainableTree: out[n] = a(x_n) * ( sin(Wt x_n + bt) . w_eff + c )
// Tree after sin() is linear with OUT=1 -> collapses to (w_eff[64], c).
// Main kernel: h = x@Wt^T + bt on HMMA (mma.sync bf16, hi/lo split packed in
// K for fp32-grade accuracy), sin + dot + envelope on FFMA.
// ===========================================================================

__device__ float g_part[16][64];   // per-leaf partials of w_eff
__device__ float c_part[16];       // per-leaf partials of c

// ---------------- helpers ----------------
__device__ __forceinline__ uint32_t bfpk(float lo, float hi) {
    uint32_t d;
    asm("cvt.rn.bf16x2.f32 %0, %1, %2;" : "=r"(d) : "f"(hi), "f"(lo));
    return d;   // lower 16 = bf16(lo), upper 16 = bf16(hi)
}
__device__ __forceinline__ float bflo(uint32_t p) { return __uint_as_float(p << 16); }
__device__ __forceinline__ float bfhi(uint32_t p) { return __uint_as_float(p & 0xffff0000u); }

// ---------------------------------------------------------------------------
// Compose: 16 blocks; block k needs only ONE matrix per level:
// W1[k>>3], W2[k>>2], W3[k>>1], Wleaf[k].
// ---------------------------------------------------------------------------
__global__ void __launch_bounds__(256)
compose_kernel(const float* __restrict__ Wleaf, const float* __restrict__ bleaf,
               const float* __restrict__ W3, const float* __restrict__ b3,
               const float* __restrict__ W2, const float* __restrict__ b2,
               const float* __restrict__ W1, const float* __restrict__ b1,
               const float* __restrict__ Wr, const float* __restrict__ br) {
    __shared__ float sW1[4096], sW2[4096];
    __shared__ float sGr[64], sG1[64], sG2[64], sG3[64];
    __shared__ float red[4][64];
    __shared__ float cp[64];

    const int t = threadIdx.x;
    const int k = blockIdx.x;
    const int o = t & 63, q = t >> 6;

    {   // bulk copy W1/W2 slices (32KB) — coalesced, high MLP
        const float4* w1 = (const float4*)(W1 + (k >> 3) * 4096);
        const float4* w2 = (const float4*)(W2 + (k >> 2) * 4096);
        float4* s1 = (float4*)sW1;
        float4* s2 = (float4*)sW2;
        #pragma unroll
        for (int i = 0; i < 4; i++) {
            s1[t + 256 * i] = w1[t + 256 * i];
            s2[t + 256 * i] = w2[t + 256 * i];
        }
    }
    if (t < 64) sGr[t] = Wr[t];
    __syncthreads();

    {   // g1[o] = sum_p W1[i][p][o] * gr[p]
        float s = 0.f;
        #pragma unroll
        for (int p = q * 16; p < q * 16 + 16; p++) s = fmaf(sW1[p * 64 + o], sGr[p], s);
        red[q][o] = s;
    }
    __syncthreads();
    if (t < 64) sG1[t] = red[0][t] + red[1][t] + red[2][t] + red[3][t];
    __syncthreads();

    {   // g2
        float s = 0.f;
        #pragma unroll
        for (int p = q * 16; p < q * 16 + 16; p++) s = fmaf(sW2[p * 64 + o], sG1[p], s);
        red[q][o] = s;
    }
    __syncthreads();
    if (t < 64) sG2[t] = red[0][t] + red[1][t] + red[2][t] + red[3][t];
    __syncthreads();

    {   // g3 (stream W3[k>>1] from global)
        const float* W = W3 + (k >> 1) * 4096;
        float s = 0.f;
        #pragma unroll
        for (int p = q * 16; p < q * 16 + 16; p++) s = fmaf(W[p * 64 + o], sG2[p], s);
        red[q][o] = s;
    }
    __syncthreads();
    if (t < 64) sG3[t] = red[0][t] + red[1][t] + red[2][t] + red[3][t];
    __syncthreads();

    {   // leaf: g_part[k][m] = sum_o g3[o] * Wleaf[k][o][m]
        const float* W = Wleaf + k * 4096;
        float s = 0.f;
        #pragma unroll
        for (int p = q * 16; p < q * 16 + 16; p++) s = fmaf(W[p * 64 + o], sG3[p], s);
        red[q][o] = s;
    }
    __syncthreads();
    if (t < 64) g_part[k][t] = red[0][t] + red[1][t] + red[2][t] + red[3][t];

    // bias partials: each term assigned to exactly one block
    if (t < 64) {
        float s = sG3[o] * bleaf[k * 64 + o];
        if ((k & 1) == 0) s = fmaf(sG2[o], b3[(k >> 1) * 64 + o], s);
        if ((k & 3) == 0) s = fmaf(sG1[o], b2[(k >> 2) * 64 + o], s);
        if (k == 0)       s = fmaf(sGr[o], b1[o] + b1[64 + o], s);
        cp[o] = s;
    }
    __syncthreads();
    if (t == 0) {
        float s = (k == 0) ? br[0] : 0.f;
        #pragma unroll 8
        for (int i = 0; i < 64; i++) s += cp[i];
        c_part[k] = s;
    }
}

// ---------------------------------------------------------------------------
// Main kernel. Per warp-iteration: 16 samples.
//   A (x) tile: 16 rows x 32 K bf16, smem rows padded to 80B (conflict-free
//   ldmatrix).  K cols: [x_hi(10) | x_lo(10) | x_hi(10) | 1, 1]
//   B (Wt) cols:        [W_hi(10) | W_hi(10) | W_lo(10) | bt_hi, bt_lo]
//   h = x_hi.W_hi + x_lo.W_hi + x_hi.W_lo + bt   (fp32 accum, ~1e-5 rel)
//   B fragments live in registers (32 regs), loaded once.
// ---------------------------------------------------------------------------
__global__ void __launch_bounds__(128, 6)
tree_main_kernel(const float* __restrict__ x, const float* __restrict__ Wt,
                 const float* __restrict__ bt, float* __restrict__ out,
                 int N, int n_chunks) {
    __shared__ uint32_t sB[64][18];       // [out][k-pair], 72B rows
    __shared__ uint32_t sA[4][16][20];    // per warp: 16 rows x 80B
    __shared__ float sWeff[64];
    __shared__ float sC[1];

    const int t = threadIdx.x;
    const int wid = t >> 5, lane = t & 31;
    const int c = lane & 3, g = lane >> 2;

    // ---- reduce w_eff / c from compose partials ----
    if (t < 64) {
        float s = 0.f;
        #pragma unroll
        for (int k = 0; k < 16; k++) s += g_part[k][t];
        sWeff[t] = s;
    }
    if (t == 64) {
        float s = 0.f;
        #pragma unroll
        for (int k = 0; k < 16; k++) s += c_part[k];
        sC[0] = s;
    }

    // ---- build B tile (thread t = output t) ----
    if (t < 64) {
        const float2* wr = (const float2*)(Wt + t * 10);
        uint32_t H[5], L[5];
        #pragma unroll
        for (int j = 0; j < 5; j++) {
            const float2 v = wr[j];
            H[j] = bfpk(v.x, v.y);
            L[j] = bfpk(v.x - bflo(H[j]), v.y - bfhi(H[j]));
        }
        const float bv = bt[t];
        const uint32_t bh = bfpk(bv, 0.f);
        const uint32_t bp = bfpk(bv, bv - bflo(bh));   // {bt_hi, bt_lo}
        #pragma unroll
        for (int j = 0; j < 5; j++) {
            sB[t][j]      = H[j];   // k 0-9  : W_hi
            sB[t][5 + j]  = H[j];   // k 10-19: W_hi
            sB[t][10 + j] = L[j];   // k 20-29: W_lo
        }
        sB[t][15] = bp;             // k 30,31: bt_hi, bt_lo
        sB[t][16] = 0u; sB[t][17] = 0u;
    }
    __syncthreads();

    // ---- load B fragments into registers (once) ----
    // mma.m16n8k16.row.col B frag: b0 = {B[2c][n], B[2c+1][n]}, b1 = {B[2c+8][n],...}
    uint32_t bf0[8][2], bf1[8][2];   // [n-tile][k-chunk]
    #pragma unroll
    for (int nt = 0; nt < 8; nt++) {
        const int row = 8 * nt + g;            // n (output) index
        #pragma unroll
        for (int kc = 0; kc < 2; kc++) {
            bf0[nt][kc] = sB[row][kc * 8 + c];
            bf1[nt][kc] = sB[row][kc * 8 + 4 + c];
        }
    }
    const float cv = sC[0];

    const int s16 = lane & 15;
    // ldmatrix x4 lane address: submats {rows0-7,k0-7},{rows8-15,k0-7},
    // {rows0-7,k8-15},{rows8-15,k8-15}
    const int lm_sub = lane >> 3, lm_r = lane & 7;
    const int lm_row = lm_r + 8 * (lm_sub & 1);
    const uint32_t lm_base =
        (uint32_t)__cvta_generic_to_shared(&sA[wid][lm_row][0]) + (lm_sub >> 1) * 16;

    const float C7f = -1.9841270e-4f, C5f = 8.3333333e-3f, C3f = -1.6666667e-1f;

    const int total_warps = gridDim.x * 4;
    for (int ch = blockIdx.x * 4 + wid; ch < n_chunks; ch += total_warps) {
        const int row = ch * 16 + s16;
        float xv[10];
        if (row < N) {
            const float2* p = (const float2*)(x + (size_t)row * 10);
            #pragma unroll
            for (int i = 0; i < 5; i++) { float2 v = p[i]; xv[2*i] = v.x; xv[2*i+1] = v.y; }
        } else {
            #pragma unroll
            for (int d = 0; d < 10; d++) xv[d] = 0.f;
        }

        // envelope
        float env = fmaf(xv[0], xv[0], -1.f);
        #pragma unroll
        for (int d = 1; d < 10; d++) env *= fmaf(xv[d], xv[d], -1.f);
        env = env * rsqrtf(fmaf(env, env, 1000.f));

        // stage A row (2 lanes per sample; lane<16 writes k-pairs 0-7, else 8-15)
        uint32_t H[5];
        #pragma unroll
        for (int j = 0; j < 5; j++) H[j] = bfpk(xv[2 * j], xv[2 * j + 1]);
        uint32_t* arow = sA[wid][s16];
        if (lane < 16) {
            const uint32_t L0 = bfpk(xv[0] - bflo(H[0]), xv[1] - bfhi(H[0]));
            const uint32_t L1 = bfpk(xv[2] - bflo(H[1]), xv[3] - bfhi(H[1]));
            const uint32_t L2 = bfpk(xv[4] - bflo(H[2]), xv[5] - bfhi(H[2]));
            *(uint4*)&arow[0] = make_uint4(H[0], H[1], H[2], H[3]);
            *(uint4*)&arow[4] = make_uint4(H[4], L0, L1, L2);
        } else {
            const uint32_t L3 = bfpk(xv[6] - bflo(H[3]), xv[7] - bfhi(H[3]));
            const uint32_t L4 = bfpk(xv[8] - bflo(H[4]), xv[9] - bfhi(H[4]));
            *(uint4*)&arow[8]  = make_uint4(L3, L4, H[0], H[1]);
            *(uint4*)&arow[12] = make_uint4(H[2], H[3], H[4], 0x3f803f80u); // ones
        }
        __syncwarp();

        uint32_t a0[4], a1[4];
        asm volatile("ldmatrix.sync.aligned.m8n8.x4.shared.b16 {%0,%1,%2,%3}, [%4];"
                     : "=r"(a0[0]), "=r"(a0[1]), "=r"(a0[2]), "=r"(a0[3])
                     : "r"(lm_base));
        asm volatile("ldmatrix.sync.aligned.m8n8.x4.shared.b16 {%0,%1,%2,%3}, [%4];"
                     : "=r"(a1[0]), "=r"(a1[1]), "=r"(a1[2]), "=r"(a1[3])
                     : "r"(lm_base + 32));

        float accA = 0.f, accB = 0.f;
        #pragma unroll
        for (int nt = 0; nt < 8; nt++) {
            float d0 = 0.f, d1 = 0.f, d2 = 0.f, d3 = 0.f;
            asm volatile(
                "mma.sync.aligned.m16n8k16.row.col.f32.bf16.bf16.f32 "
                "{%0,%1,%2,%3}, {%4,%5,%6,%7}, {%8,%9}, {%0,%1,%2,%3};"
                : "+f"(d0), "+f"(d1), "+f"(d2), "+f"(d3)
                : "r"(a0[0]), "r"(a0[1]), "r"(a0[2]), "r"(a0[3]),
                  "r"(bf0[nt][0]), "r"(bf1[nt][0]));
            asm volatile(
                "mma.sync.aligned.m16n8k16.row.col.f32.bf16.bf16.f32 "
                "{%0,%1,%2,%3}, {%4,%5,%6,%7}, {%8,%9}, {%0,%1,%2,%3};"
                : "+f"(d0), "+f"(d1), "+f"(d2), "+f"(d3)
                : "r"(a1[0]), "r"(a1[1]), "r"(a1[2]), "r"(a1[3]),
                  "r"(bf0[nt][1]), "r"(bf1[nt][1]));

            const float2 wv = *(const float2*)&sWeff[8 * nt + 2 * c];
            {   // sample g, output 8nt+2c
                const float t2 = d0 * d0;
                float p = fmaf(t2, C7f, C5f); p = fmaf(t2, p, C3f); p = fmaf(t2, p, 1.f);
                accA = fmaf(d0 * wv.x, p, accA);
            }
            {   // sample g, output 8nt+2c+1
                const float t2 = d1 * d1;
                float p = fmaf(t2, C7f, C5f); p = fmaf(t2, p, C3f); p = fmaf(t2, p, 1.f);
                accA = fmaf(d1 * wv.y, p, accA);
            }
            {   // sample g+8, output 8nt+2c
                const float t2 = d2 * d2;
                float p = fmaf(t2, C7f, C5f); p = fmaf(t2, p, C3f); p = fmaf(t2, p, 1.f);
                accB = fmaf(d2 * wv.x, p, accB);
            }
            {   // sample g+8, output 8nt+2c+1
                const float t2 = d3 * d3;
                float p = fmaf(t2, C7f, C5f); p = fmaf(t2, p, C3f); p = fmaf(t2, p, 1.f);
                accB = fmaf(d3 * wv.y, p, accB);
            }
        }

        // reduce over the 4 lanes (c=0..3) sharing the same sample rows
        accA += __shfl_xor_sync(0xffffffffu, accA, 1);
        accA += __shfl_xor_sync(0xffffffffu, accA, 2);
        accB += __shfl_xor_sync(0xffffffffu, accB, 1);
        accB += __shfl_xor_sync(0xffffffffu, accB, 2);

        const float envG  = __shfl_sync(0xffffffffu, env, g);
        const float envG8 = __shfl_sync(0xffffffffu, env, g + 8);

        const int base = ch * 16;
        if (c == 0 && base + g < N)     out[base + g]     = envG  * (accA + cv);
        if (c == 1 && base + g + 8 < N) out[base + g + 8] = envG8 * (accB + cv);
    }
}

// ---------------------------------------------------------------------------
extern "C" void kernel_launch(void* const* d_in, const int* in_sizes, int n_in,
                              void* d_out, int out_size) {
    const float* x     = (const float*)d_in[0];
    const float* Wt    = (const float*)d_in[1];
    const float* bt    = (const float*)d_in[2];
    const float* Wleaf = (const float*)d_in[3];
    const float* bleaf = (const float*)d_in[4];
    const float* W3    = (const float*)d_in[5];
    const float* b3    = (const float*)d_in[6];
    const float* W2    = (const float*)d_in[7];
    const float* b2    = (const float*)d_in[8];
    const float* W1    = (const float*)d_in[9];
    const float* b1    = (const float*)d_in[10];
    const float* Wr    = (const float*)d_in[11];
    const float* br    = (const float*)d_in[12];
    float* out = (float*)d_out;

    const int N = in_sizes[0] / 10;
    const int n_chunks = (N + 15) / 16;

    compose_kernel<<<16, 256>>>(Wleaf, bleaf, W3, b3, W2, b2, W1, b1, Wr, br);

    int grid = (n_chunks + 3) / 4;
    if (grid > 1024) grid = 1024;
    tree_main_kernel<<<grid, 128>>>(x, Wt, bt, out, N, n_chunks);
}

// round 5
// speedup vs baseline: 1.6842x; 1.1579x over previous
#include <cuda_runtime.h>
#include <cuda_bf16.h>
#include <cstdint>

// ===========================================================================
// TrainableTree: out[n] = a(x_n) * ( sin(Wt x_n + bt) . w_eff + c )
// Tree after sin() is linear with OUT=1 -> collapses to (w_eff[64], c).
// Main kernel: h = x@Wt^T + bt on HMMA (mma.sync bf16, hi/lo split packed in
// K for fp32-grade accuracy), sin on MUFU (sin.approx), dot + envelope FFMA.
// ===========================================================================

__device__ float g_part[16][64];   // per-leaf partials of w_eff
__device__ float c_part[16];       // per-leaf partials of c

// ---------------- helpers ----------------
__device__ __forceinline__ uint32_t bfpk(float lo, float hi) {
    uint32_t d;
    asm("cvt.rn.bf16x2.f32 %0, %1, %2;" : "=r"(d) : "f"(hi), "f"(lo));
    return d;   // lower 16 = bf16(lo), upper 16 = bf16(hi)
}
__device__ __forceinline__ float bflo(uint32_t p) { return __uint_as_float(p << 16); }
__device__ __forceinline__ float bfhi(uint32_t p) { return __uint_as_float(p & 0xffff0000u); }

// ---------------------------------------------------------------------------
// Compose: 16 blocks; block k needs only ONE matrix per level:
// W1[k>>3], W2[k>>2], W3[k>>1], Wleaf[k].
// ---------------------------------------------------------------------------
__global__ void __launch_bounds__(256)
compose_kernel(const float* __restrict__ Wleaf, const float* __restrict__ bleaf,
               const float* __restrict__ W3, const float* __restrict__ b3,
               const float* __restrict__ W2, const float* __restrict__ b2,
               const float* __restrict__ W1, const float* __restrict__ b1,
               const float* __restrict__ Wr, const float* __restrict__ br) {
    __shared__ float sW1[4096], sW2[4096];
    __shared__ float sGr[64], sG1[64], sG2[64], sG3[64];
    __shared__ float red[4][64];
    __shared__ float cp[64];

    const int t = threadIdx.x;
    const int k = blockIdx.x;
    const int o = t & 63, q = t >> 6;

    {   // bulk copy W1/W2 slices (32KB) — coalesced, high MLP
        const float4* w1 = (const float4*)(W1 + (k >> 3) * 4096);
        const float4* w2 = (const float4*)(W2 + (k >> 2) * 4096);
        float4* s1 = (float4*)sW1;
        float4* s2 = (float4*)sW2;
        #pragma unroll
        for (int i = 0; i < 4; i++) {
            s1[t + 256 * i] = w1[t + 256 * i];
            s2[t + 256 * i] = w2[t + 256 * i];
        }
    }
    if (t < 64) sGr[t] = Wr[t];
    __syncthreads();

    {   // g1[o] = sum_p W1[i][p][o] * gr[p]
        float s = 0.f;
        #pragma unroll
        for (int p = q * 16; p < q * 16 + 16; p++) s = fmaf(sW1[p * 64 + o], sGr[p], s);
        red[q][o] = s;
    }
    __syncthreads();
    if (t < 64) sG1[t] = red[0][t] + red[1][t] + red[2][t] + red[3][t];
    __syncthreads();

    {   // g2
        float s = 0.f;
        #pragma unroll
        for (int p = q * 16; p < q * 16 + 16; p++) s = fmaf(sW2[p * 64 + o], sG1[p], s);
        red[q][o] = s;
    }
    __syncthreads();
    if (t < 64) sG2[t] = red[0][t] + red[1][t] + red[2][t] + red[3][t];
    __syncthreads();

    {   // g3 (stream W3[k>>1] from global)
        const float* W = W3 + (k >> 1) * 4096;
        float s = 0.f;
        #pragma unroll
        for (int p = q * 16; p < q * 16 + 16; p++) s = fmaf(W[p * 64 + o], sG2[p], s);
        red[q][o] = s;
    }
    __syncthreads();
    if (t < 64) sG3[t] = red[0][t] + red[1][t] + red[2][t] + red[3][t];
    __syncthreads();

    {   // leaf: g_part[k][m] = sum_o g3[o] * Wleaf[k][o][m]
        const float* W = Wleaf + k * 4096;
        float s = 0.f;
        #pragma unroll
        for (int p = q * 16; p < q * 16 + 16; p++) s = fmaf(W[p * 64 + o], sG3[p], s);
        red[q][o] = s;
    }
    __syncthreads();
    if (t < 64) g_part[k][t] = red[0][t] + red[1][t] + red[2][t] + red[3][t];

    // bias partials: each term assigned to exactly one block
    if (t < 64) {
        float s = sG3[o] * bleaf[k * 64 + o];
        if ((k & 1) == 0) s = fmaf(sG2[o], b3[(k >> 1) * 64 + o], s);
        if ((k & 3) == 0) s = fmaf(sG1[o], b2[(k >> 2) * 64 + o], s);
        if (k == 0)       s = fmaf(sGr[o], b1[o] + b1[64 + o], s);
        cp[o] = s;
    }
    __syncthreads();
    if (t == 0) {
        float s = (k == 0) ? br[0] : 0.f;
        #pragma unroll 8
        for (int i = 0; i < 64; i++) s += cp[i];
        c_part[k] = s;
    }
}

// ---------------------------------------------------------------------------
// Main kernel. Per warp-iteration: 16 samples.
//   A (x) tile: 16 rows x 32 K bf16, smem rows padded to 80B (conflict-free
//   ldmatrix).  K cols: [x_hi(10) | x_lo(10) | x_hi(10) | 1, 1]
//   B (Wt) cols:        [W_hi(10) | W_hi(10) | W_lo(10) | bt_hi, bt_lo]
//   h = x_hi.W_hi + x_lo.W_hi + x_hi.W_lo + bt   (fp32 accum, ~1e-5 rel)
//   B fragments live in registers (32 regs), loaded once.
//   Epilogue: MUFU sin.approx + 1 FFMA per h value.
// ---------------------------------------------------------------------------
__global__ void __launch_bounds__(128, 6)
tree_main_kernel(const float* __restrict__ x, const float* __restrict__ Wt,
                 const float* __restrict__ bt, float* __restrict__ out,
                 int N, int n_chunks) {
    __shared__ uint32_t sB[64][18];       // [out][k-pair], 72B rows
    __shared__ uint32_t sA[4][16][20];    // per warp: 16 rows x 80B
    __shared__ float sWeff[64];
    __shared__ float sC[1];

    const int t = threadIdx.x;
    const int wid = t >> 5, lane = t & 31;
    const int c = lane & 3, g = lane >> 2;

    // ---- reduce w_eff / c from compose partials ----
    if (t < 64) {
        float s = 0.f;
        #pragma unroll
        for (int k = 0; k < 16; k++) s += g_part[k][t];
        sWeff[t] = s;
    }
    if (t == 64) {
        float s = 0.f;
        #pragma unroll
        for (int k = 0; k < 16; k++) s += c_part[k];
        sC[0] = s;
    }

    // ---- build B tile (thread t = output t) ----
    if (t < 64) {
        const float2* wr = (const float2*)(Wt + t * 10);
        uint32_t H[5], L[5];
        #pragma unroll
        for (int j = 0; j < 5; j++) {
            const float2 v = wr[j];
            H[j] = bfpk(v.x, v.y);
            L[j] = bfpk(v.x - bflo(H[j]), v.y - bfhi(H[j]));
        }
        const float bv = bt[t];
        const uint32_t bh = bfpk(bv, 0.f);
        const uint32_t bp = bfpk(bv, bv - bflo(bh));   // {bt_hi, bt_lo}
        #pragma unroll
        for (int j = 0; j < 5; j++) {
            sB[t][j]      = H[j];   // k 0-9  : W_hi
            sB[t][5 + j]  = H[j];   // k 10-19: W_hi
            sB[t][10 + j] = L[j];   // k 20-29: W_lo
        }
        sB[t][15] = bp;             // k 30,31: bt_hi, bt_lo
        sB[t][16] = 0u; sB[t][17] = 0u;
    }
    __syncthreads();

    // ---- load B fragments into registers (once) ----
    uint32_t bf0[8][2], bf1[8][2];   // [n-tile][k-chunk]
    #pragma unroll
    for (int nt = 0; nt < 8; nt++) {
        const int row = 8 * nt + g;            // n (output) index
        #pragma unroll
        for (int kc = 0; kc < 2; kc++) {
            bf0[nt][kc] = sB[row][kc * 8 + c];
            bf1[nt][kc] = sB[row][kc * 8 + 4 + c];
        }
    }
    const float cv = sC[0];

    const int s16 = lane & 15;
    const int lm_sub = lane >> 3, lm_r = lane & 7;
    const int lm_row = lm_r + 8 * (lm_sub & 1);
    const uint32_t lm_base =
        (uint32_t)__cvta_generic_to_shared(&sA[wid][lm_row][0]) + (lm_sub >> 1) * 16;

    const int total_warps = gridDim.x * 4;
    for (int ch = blockIdx.x * 4 + wid; ch < n_chunks; ch += total_warps) {
        const int row = ch * 16 + s16;
        float xv[10];
        if (row < N) {
            const float2* p = (const float2*)(x + (size_t)row * 10);
            #pragma unroll
            for (int i = 0; i < 5; i++) { float2 v = p[i]; xv[2*i] = v.x; xv[2*i+1] = v.y; }
        } else {
            #pragma unroll
            for (int d = 0; d < 10; d++) xv[d] = 0.f;
        }

        // envelope
        float env = fmaf(xv[0], xv[0], -1.f);
        #pragma unroll
        for (int d = 1; d < 10; d++) env *= fmaf(xv[d], xv[d], -1.f);
        env = env * rsqrtf(fmaf(env, env, 1000.f));

        // stage A row (2 lanes per sample; lane<16 writes k-pairs 0-7, else 8-15)
        uint32_t H[5];
        #pragma unroll
        for (int j = 0; j < 5; j++) H[j] = bfpk(xv[2 * j], xv[2 * j + 1]);
        uint32_t* arow = sA[wid][s16];
        if (lane < 16) {
            const uint32_t L0 = bfpk(xv[0] - bflo(H[0]), xv[1] - bfhi(H[0]));
            const uint32_t L1 = bfpk(xv[2] - bflo(H[1]), xv[3] - bfhi(H[1]));
            const uint32_t L2 = bfpk(xv[4] - bflo(H[2]), xv[5] - bfhi(H[2]));
            *(uint4*)&arow[0] = make_uint4(H[0], H[1], H[2], H[3]);
            *(uint4*)&arow[4] = make_uint4(H[4], L0, L1, L2);
        } else {
            const uint32_t L3 = bfpk(xv[6] - bflo(H[3]), xv[7] - bfhi(H[3]));
            const uint32_t L4 = bfpk(xv[8] - bflo(H[4]), xv[9] - bfhi(H[4]));
            *(uint4*)&arow[8]  = make_uint4(L3, L4, H[0], H[1]);
            *(uint4*)&arow[12] = make_uint4(H[2], H[3], H[4], 0x3f803f80u); // ones
        }
        __syncwarp();

        uint32_t a0[4], a1[4];
        asm volatile("ldmatrix.sync.aligned.m8n8.x4.shared.b16 {%0,%1,%2,%3}, [%4];"
                     : "=r"(a0[0]), "=r"(a0[1]), "=r"(a0[2]), "=r"(a0[3])
                     : "r"(lm_base));
        asm volatile("ldmatrix.sync.aligned.m8n8.x4.shared.b16 {%0,%1,%2,%3}, [%4];"
                     : "=r"(a1[0]), "=r"(a1[1]), "=r"(a1[2]), "=r"(a1[3])
                     : "r"(lm_base + 32));

        float accA = 0.f, accB = 0.f;
        #pragma unroll
        for (int nt = 0; nt < 8; nt++) {
            float d0 = 0.f, d1 = 0.f, d2 = 0.f, d3 = 0.f;
            asm volatile(
                "mma.sync.aligned.m16n8k16.row.col.f32.bf16.bf16.f32 "
                "{%0,%1,%2,%3}, {%4,%5,%6,%7}, {%8,%9}, {%0,%1,%2,%3};"
                : "+f"(d0), "+f"(d1), "+f"(d2), "+f"(d3)
                : "r"(a0[0]), "r"(a0[1]), "r"(a0[2]), "r"(a0[3]),
                  "r"(bf0[nt][0]), "r"(bf1[nt][0]));
            asm volatile(
                "mma.sync.aligned.m16n8k16.row.col.f32.bf16.bf16.f32 "
                "{%0,%1,%2,%3}, {%4,%5,%6,%7}, {%8,%9}, {%0,%1,%2,%3};"
                : "+f"(d0), "+f"(d1), "+f"(d2), "+f"(d3)
                : "r"(a1[0]), "r"(a1[1]), "r"(a1[2]), "r"(a1[3]),
                  "r"(bf0[nt][1]), "r"(bf1[nt][1]));

            const float2 wv = *(const float2*)&sWeff[8 * nt + 2 * c];
            // MUFU sin.approx + single FFMA per h value
            float s0, s1v, s2v, s3v;
            asm("sin.approx.f32 %0, %1;" : "=f"(s0)  : "f"(d0));
            asm("sin.approx.f32 %0, %1;" : "=f"(s1v) : "f"(d1));
            asm("sin.approx.f32 %0, %1;" : "=f"(s2v) : "f"(d2));
            asm("sin.approx.f32 %0, %1;" : "=f"(s3v) : "f"(d3));
            accA = fmaf(s0,  wv.x, accA);
            accA = fmaf(s1v, wv.y, accA);
            accB = fmaf(s2v, wv.x, accB);
            accB = fmaf(s3v, wv.y, accB);
        }

        // reduce over the 4 lanes (c=0..3) sharing the same sample rows
        accA += __shfl_xor_sync(0xffffffffu, accA, 1);
        accA += __shfl_xor_sync(0xffffffffu, accA, 2);
        accB += __shfl_xor_sync(0xffffffffu, accB, 1);
        accB += __shfl_xor_sync(0xffffffffu, accB, 2);

        const float envG  = __shfl_sync(0xffffffffu, env, g);
        const float envG8 = __shfl_sync(0xffffffffu, env, g + 8);

        const int base = ch * 16;
        if (c == 0 && base + g < N)     out[base + g]     = envG  * (accA + cv);
        if (c == 1 && base + g + 8 < N) out[base + g + 8] = envG8 * (accB + cv);
    }
}

// ---------------------------------------------------------------------------
extern "C" void kernel_launch(void* const* d_in, const int* in_sizes, int n_in,
                              void* d_out, int out_size) {
    const float* x     = (const float*)d_in[0];
    const float* Wt    = (const float*)d_in[1];
    const float* bt    = (const float*)d_in[2];
    const float* Wleaf = (const float*)d_in[3];
    const float* bleaf = (const float*)d_in[4];
    const float* W3    = (const float*)d_in[5];
    const float* b3    = (const float*)d_in[6];
    const float* W2    = (const float*)d_in[7];
    const float* b2    = (const float*)d_in[8];
    const float* W1    = (const float*)d_in[9];
    const float* b1    = (const float*)d_in[10];
    const float* Wr    = (const float*)d_in[11];
    const float* br    = (const float*)d_in[12];
    float* out = (float*)d_out;

    const int N = in_sizes[0] / 10;
    const int n_chunks = (N + 15) / 16;

    compose_kernel<<<16, 256>>>(Wleaf, bleaf, W3, b3, W2, b2, W1, b1, Wr, br);

    // 148 SMs x 6 resident blocks -> one balanced wave, stride loop
    int grid = 148 * 6;
    int max_grid = (n_chunks + 3) / 4;
    if (grid > max_grid) grid = max_grid;
    tree_main_kernel<<<grid, 128>>>(x, Wt, bt, out, N, n_chunks);
}